// round 12
// baseline (speedup 1.0000x reference)
#include <cuda_runtime.h>
#include <math.h>

typedef unsigned long long ull;

constexpr int NAT = 64;
constexpr int NE  = 512;
constexpr int NA  = 65;
constexpr int NUMEL = 10;
constexpr int CH  = 128;    // chunk width (edges)
constexpr int TP  = 128;    // tile pitch (floats)
constexpr int HP  = 68;     // Hs pitch
constexpr int KP  = 68;     // Km pitch (16B-aligned rows)
constexpr int FP  = 68;     // Fm pitch
constexpr int NTH = 384;    // 12 warps

// ---- shared memory byte offsets ----
constexpr int OFF_WD  = 0;                       // double wd[65]
constexpr int OFF_CWD = 528;                     // double cwd[65]
constexpr int OFF_T0  = 1584;                    // float tile0[65][128] (raw T + ones row)
constexpr int OFF_T1  = OFF_T0 + 65*TP*4;        // 34864: tile1
constexpr int TILES_END = OFF_T1 + 65*TP*4;      // 68144
constexpr int OFF_KM  = OFF_T0;                  // float Km[65][68]  (aliases tiles)
constexpr int OFF_FM  = OFF_KM + 65*KP*4 + 16;   // float Fm[65][68]  (aliases tiles)
constexpr int OFF_AS  = TILES_END;               // float As[64][64]
constexpr int OFF_HS  = OFF_AS + 64*64*4;        // float Hs[65][68]
constexpr int OFF_DV  = OFF_HS + 65*HP*4;        // float dinv_e[512]
constexpr int OFF_PX  = OFF_DV + 2048;
constexpr int OFF_PY  = OFF_PX + 256;
constexpr int OFF_PZ  = OFF_PY + 256;
constexpr int OFF_EN  = OFF_PZ + 256;
constexpr int OFF_DG  = OFF_EN + 256;
constexpr int OFF_RR  = OFF_DG + 256;
constexpr int OFF_RF  = OFF_RR + 256;            // float rf[68]
constexpr int OFF_RG  = OFF_RF + 272;            // float rg[68]
constexpr int OFF_DI  = OFF_RG + 272;            // float dinv[68] (GJ pivots)
constexpr int OFF_PH  = OFF_DI + 272;            // int pivhist[68]
constexpr int SMEM_BYTES = OFF_PH + 272;         // ~104.4 KB -> 2 CTAs/SM

static_assert(OFF_FM + 65*FP*4 <= TILES_END, "Km/Fm must fit in tile region");

__device__ __forceinline__ ull ffma2(ull a, ull b, ull c) {
    ull d; asm("fma.rn.f32x2 %0, %1, %2, %3;" : "=l"(d) : "l"(a), "l"(b), "l"(c)); return d;
}
__device__ __forceinline__ ull fadd2(ull a, ull b) {
    ull d; asm("add.rn.f32x2 %0, %1, %2;" : "=l"(d) : "l"(a), "l"(b)); return d;
}
__device__ __forceinline__ ull fmul2(ull a, ull b) {
    ull d; asm("mul.rn.f32x2 %0, %1, %2;" : "=l"(d) : "l"(a), "l"(b)); return d;
}
__device__ __forceinline__ float2 unpack2(ull v) {
    float2 f; asm("mov.b64 {%0,%1}, %2;" : "=f"(f.x), "=f"(f.y) : "l"(v)); return f;
}
__device__ __forceinline__ ull dup2(float f) {
    ull d; asm("mov.b64 %0, {%1, %1};" : "=l"(d) : "f"(f)); return d;
}
__device__ __forceinline__ unsigned int pivkey(float v, int row) {
    return (__float_as_uint(fabsf(v)) & 0xFFFFFF80u) | (unsigned int)row;
}
__device__ __forceinline__ unsigned int smem_u32(const void* p) {
    unsigned int a;
    asm("{ .reg .u64 t; cvta.to.shared.u64 t, %1; cvt.u32.u64 %0, t; }" : "=r"(a) : "l"(p));
    return a;
}
// stream one 64x128 raw T chunk into a tile buffer (rows 0..63)
__device__ __forceinline__ void issue_chunk(const float* Tm, unsigned int tile_s,
                                            int base, int t) {
    for (int idx = t; idx < 2048; idx += NTH) {          // 2048 float4
        int row = idx >> 5;
        int c4  = (idx & 31) << 2;                        // col (floats)
        const float* src = Tm + row * NE + base + c4;
        unsigned int dst = tile_s + (row << 9) + (c4 << 2);
        asm volatile("cp.async.ca.shared.global [%0], [%1], 16;" :: "r"(dst), "l"(src) : "memory");
    }
    asm volatile("cp.async.commit_group;" ::: "memory");
}

__global__ __launch_bounds__(NTH, 2)
void cheq_kernel(const float* __restrict__ positions,
                 const float* __restrict__ T,
                 const float* __restrict__ eneg,
                 const float* __restrict__ node_attrs,
                 const float* __restrict__ total_charge,
                 const float* __restrict__ hardness,
                 const float* __restrict__ cov_radii,
                 const int*   __restrict__ atomic_numbers,
                 const int*   __restrict__ edge_index,
                 float* __restrict__ out)
{
    extern __shared__ __align__(16) unsigned char sm[];
    double* wd  = (double*)(sm + OFF_WD);
    double* cwd = (double*)(sm + OFF_CWD);
    float* Km  = (float*)(sm + OFF_KM);
    float* Fm  = (float*)(sm + OFF_FM);
    float* As  = (float*)(sm + OFF_AS);
    float* Hs  = (float*)(sm + OFF_HS);
    float* dve = (float*)(sm + OFF_DV);
    float* px  = (float*)(sm + OFF_PX);
    float* py  = (float*)(sm + OFF_PY);
    float* pz  = (float*)(sm + OFF_PZ);
    float* ens = (float*)(sm + OFF_EN);
    float* dgs = (float*)(sm + OFF_DG);
    float* rrs = (float*)(sm + OFF_RR);
    float* rf  = (float*)(sm + OFF_RF);
    float* rg  = (float*)(sm + OFF_RG);
    float* dinv= (float*)(sm + OFF_DI);
    int*   pivhist = (int*)(sm + OFF_PH);

    const unsigned int sbase = smem_u32(sm);
    const int mol = blockIdx.x;
    const int t = threadIdx.x;
    const int lane = t & 31;
    const int w = t >> 5;
    const float* Tm = T + (size_t)mol * (NAT * NE);
    const float* pm = positions + mol * NAT * 3;
    const int* eim = edge_index + mol * 2 * NE;
    const float q = total_charge[mol];

    // ---- prologue: start streaming chunks 0 and 1 immediately ----
    issue_chunk(Tm, sbase + OFF_T0, 0, t);
    issue_chunk(Tm, sbase + OFF_T1, CH, t);

    // ones-row (row 64 of V) — written once per buffer, never overwritten
    if (t < 32) {
        float4 one4 = make_float4(1.f, 1.f, 1.f, 1.f);
        ((float4*)(sm + OFF_T0 + 64 * 512))[t] = one4;
        ((float4*)(sm + OFF_T1 + 64 * 512))[t] = one4;
    }

    // ---- per-atom small loads ----
    if (t < NAT) {
        px[t] = pm[3*t+0]; py[t] = pm[3*t+1]; pz[t] = pm[3*t+2];
        ens[t] = eneg[mol * NAT + t];
        float r = cov_radii[atomic_numbers[mol * NAT + t]];
        rrs[t] = r * r;
        const float* na = node_attrs + (size_t)(mol * NAT + t) * NUMEL;
        float best = na[0]; int bi = 0;
        #pragma unroll
        for (int j = 1; j < NUMEL; j++) { float v = na[j]; if (v > best) { best = v; bi = j; } }
        dgs[t] = hardness[bi] + 0.5641895835477563f / r;
    }
    __syncthreads();

    // ---- A matrix (64x64, symmetric): lower triangle, mirrored store ----
    for (int p = t; p < 2080; p += NTH) {
        int i = (int)((sqrtf(8.0f * p + 1.0f) - 1.0f) * 0.5f);
        while ((i + 1) * (i + 2) / 2 <= p) ++i;
        while (i * (i + 1) / 2 > p) --i;
        int j = p - i * (i + 1) / 2;
        float v;
        if (i == j) v = dgs[i];
        else {
            float dx = px[i]-px[j], dy = py[i]-py[j], dz = pz[i]-pz[j];
            float d = sqrtf(dx*dx + dy*dy + dz*dz);
            float arg = d * rsqrtf(2.0f * (rrs[i] + rrs[j]));
            v = erff(arg) / d;
        }
        As[i * 64 + j] = v;
        As[j * 64 + i] = v;
    }

    // ---- edges: dve[e] = 1/cut (cancellation-free, no sqrt) ----
    for (int e = t; e < NE; e += NTH) {
        int a0 = eim[e], a1 = eim[NE + e];
        float dx = px[a0]-px[a1], dy = py[a0]-py[a1], dz = pz[a0]-pz[a1];
        float ed = sqrtf(dx*dx + dy*dy + dz*dz);
        float th = 0.15707963267948966f * ed;
        float sh = sinf(0.5f * th);
        float ct = cosf(th);
        dve[e] = fmaxf(ct / (2.0f * sh * sh), 1e-30f);
    }

    // ---- syrk tile geometry (91 triangular 5x5 tiles; 12 warps x 4 groups x 2 rounds) ----
    const int g  = (lane >> 3);
    const int l8 = lane & 7;
    int tiR[2], tjR[2]; bool actR[2];
    #pragma unroll
    for (int r = 0; r < 2; r++) {
        int p = r * 48 + w * 4 + g;
        actR[r] = (p < 91);
        int pp = actR[r] ? p : 0;
        int ti = (int)((sqrtf(8.0f * pp + 1.0f) - 1.0f) * 0.5f);
        while ((ti + 1) * (ti + 2) / 2 <= pp) ++ti;
        while (ti * (ti + 1) / 2 > pp) --ti;
        tiR[r] = ti; tjR[r] = pp - ti * (ti + 1) / 2;
    }

    // ---- chunk loop: H = V D^-1 V^T, cp.async double-buffered ----
    for (int c = 0; c < 4; c++) {
        if (c < 3) asm volatile("cp.async.wait_group 1;" ::: "memory");
        else       asm volatile("cp.async.wait_group 0;" ::: "memory");
        __syncthreads();

        const float* tp = (const float*)(sm + ((c & 1) ? OFF_T1 : OFF_T0));
        const float* dv = dve + c * CH;
        #pragma unroll
        for (int r = 0; r < 2; r++) {
            const float* Wa = tp + (tiR[r] * 5) * TP;
            const float* Wb = tp + (tjR[r] * 5) * TP;
            const bool diag = (tiR[r] == tjR[r]);
            ull acc[25];
            #pragma unroll
            for (int m = 0; m < 25; m++) acc[m] = 0ull;
            #pragma unroll
            for (int k = 0; k < 4; k++) {
                int e = 4 * l8 + 32 * k;
                ulonglong2 dvv = *(const ulonglong2*)(dv + e);
                ulonglong2 av[5];
                #pragma unroll
                for (int i = 0; i < 5; i++)
                    av[i] = *(const ulonglong2*)(Wa + i * TP + e);
                #pragma unroll
                for (int j = 0; j < 5; j++) {
                    ulonglong2 bv = diag ? av[j] : *(const ulonglong2*)(Wb + j * TP + e);
                    ull bsx = fmul2(bv.x, dvv.x);
                    ull bsy = fmul2(bv.y, dvv.y);
                    #pragma unroll
                    for (int i = 0; i < 5; i++) {
                        acc[i*5+j] = ffma2(av[i].x, bsx, acc[i*5+j]);
                        acc[i*5+j] = ffma2(av[i].y, bsy, acc[i*5+j]);
                    }
                }
            }
            #pragma unroll
            for (int m = 0; m < 25; m++) {
                acc[m] = fadd2(acc[m], __shfl_down_sync(0xffffffffu, acc[m], 4));
                acc[m] = fadd2(acc[m], __shfl_down_sync(0xffffffffu, acc[m], 2));
                acc[m] = fadd2(acc[m], __shfl_down_sync(0xffffffffu, acc[m], 1));
            }
            if (actR[r] && l8 == 0) {
                int ti = tiR[r], tj = tjR[r];
                #pragma unroll
                for (int i = 0; i < 5; i++)
                    #pragma unroll
                    for (int j = 0; j < 5; j++) {
                        float2 f = unpack2(acc[i*5+j]);
                        float v = f.x + f.y;
                        int lo = (ti*5+i) * HP + (tj*5+j);
                        if (c == 0) Hs[lo] = v; else Hs[lo] += v;
                        if (ti != tj) {
                            int up = (tj*5+j) * HP + (ti*5+i);
                            if (c == 0) Hs[up] = v; else Hs[up] += v;
                        }
                    }
            }
        }
        __syncthreads();
        if (c + 2 < 4)
            issue_chunk(Tm, sbase + ((c & 1) ? OFF_T1 : OFF_T0), (c + 2) * CH, t);
    }

    // ---- K = I + H*C; rhs col 65 = -H*u (fp64); col 64 = delta - H col64 ----
    for (int a = w; a < NA; a += 12) {
        const float* Hr = Hs + a * HP;
        double acc = 0.0;
        for (int k2 = lane; k2 < NA; k2 += 32) {
            float uk = (k2 < 64) ? ens[k2] : q;
            acc += (double)Hr[k2] * (double)uk;
        }
        #pragma unroll
        for (int off = 16; off; off >>= 1) acc += __shfl_down_sync(0xffffffffu, acc, off);
        if (lane == 0) Km[a * KP + 65] = (float)(-acc);
    }
    if (t < NA)
        Km[t * KP + 64] = ((t == 64) ? 1.0f : 0.0f) - Hs[t * HP + 64];
    {
        const int half = lane >> 4;
        const int c0 = (lane & 15) * 4;
        #pragma unroll
        for (int pass = 0; pass < 3; pass++) {
            int a = pass * 24 + w * 2 + half;
            if (a < NA) {
                const float* Hr = Hs + a * HP;
                ull acc0 = 0ull, acc1 = 0ull;
                #pragma unroll 4
                for (int k4 = 0; k4 < 16; k4++) {
                    float4 hv = *(const float4*)(Hr + k4 * 4);
                    ulonglong2 a0 = *(const ulonglong2*)(As + (k4*4+0) * 64 + c0);
                    ulonglong2 a1 = *(const ulonglong2*)(As + (k4*4+1) * 64 + c0);
                    ulonglong2 a2 = *(const ulonglong2*)(As + (k4*4+2) * 64 + c0);
                    ulonglong2 a3 = *(const ulonglong2*)(As + (k4*4+3) * 64 + c0);
                    ull h0 = dup2(hv.x), h1 = dup2(hv.y), h2 = dup2(hv.z), h3 = dup2(hv.w);
                    acc0 = ffma2(h0, a0.x, acc0); acc1 = ffma2(h0, a0.y, acc1);
                    acc0 = ffma2(h1, a1.x, acc0); acc1 = ffma2(h1, a1.y, acc1);
                    acc0 = ffma2(h2, a2.x, acc0); acc1 = ffma2(h2, a2.y, acc1);
                    acc0 = ffma2(h3, a3.x, acc0); acc1 = ffma2(h3, a3.y, acc1);
                }
                float2 f0 = unpack2(acc0), f1 = unpack2(acc1);
                float4 v;
                v.x = f0.x + ((a == c0+0) ? 1.0f : 0.0f);
                v.y = f0.y + ((a == c0+1) ? 1.0f : 0.0f);
                v.z = f1.x + ((a == c0+2) ? 1.0f : 0.0f);
                v.w = f1.y + ((a == c0+3) ? 1.0f : 0.0f);
                *(float4*)(Km + a * KP + c0) = v;
            }
        }
    }
    __syncthreads();

    // ---- Gauss-Jordan: register-resident columns, REDUX pivot select ----
    {
        const int cols0 = (w < 6) ? 6 : 5;
        float cv0[6], cv1[6], cv2[6];
        #pragma unroll
        for (int c = 0; c < 6; c++) {
            cv0[c] = 0.f; cv1[c] = 0.f; cv2[c] = 0.f;
            int j = w + 12 * c;
            if (c < cols0) {
                cv0[c] = Km[lane * KP + j];
                cv1[c] = Km[(lane + 32) * KP + j];
                if (lane == 0) cv2[c] = Km[64 * KP + j];
            }
        }
        bool piv0 = false, piv1 = false, piv2 = false;
        if (w == 0) {
            Fm[lane] = cv0[0];
            Fm[lane + 32] = cv1[0];
            if (lane == 0) Fm[64] = cv2[0];
            unsigned int key = pivkey(cv0[0], lane);
            unsigned int k1  = pivkey(cv1[0], lane + 32);
            if (k1 > key) key = k1;
            if (lane == 0) { unsigned int k2 = pivkey(cv2[0], 64); if (k2 > key) key = k2; }
            key = __reduce_max_sync(0xffffffffu, key);
            int prow = (int)(key & 0x7Fu);
            if (prow < 32) { if (lane == prow)      { pivhist[0] = prow; dinv[0] = 1.0f / cv0[0]; } }
            else if (prow < 64) { if (lane == prow - 32) { pivhist[0] = prow; dinv[0] = 1.0f / cv1[0]; } }
            else { if (lane == 0)                  { pivhist[0] = 64;   dinv[0] = 1.0f / cv2[0]; } }
        }
        __syncthreads();

        for (int k = 0; k < NA; k++) {
            int pk = pivhist[k];
            float dk = dinv[k];
            float m0 = Fm[k * FP + lane] * dk;
            float m1 = Fm[k * FP + lane + 32] * dk;
            float m2 = Fm[k * FP + 64] * dk;
            if (lane == pk)      { m0 = 0.f; piv0 = true; }
            if (lane + 32 == pk) { m1 = 0.f; piv1 = true; }
            if (pk == 64)        { m2 = 0.f; piv2 = true; }
            int nk = k + 1;
            bool owner = (nk < NA) && (w == (nk % 12));
            if (owner) {
                #pragma unroll
                for (int c = 0; c < 6; c++) {
                    if (c < cols0 && (w + 12 * c) == nk) {
                        float src = (pk < 32) ? cv0[c] : ((pk < 64) ? cv1[c] : cv2[c]);
                        float pv = __shfl_sync(0xffffffffu, src, pk & 31);
                        float v0 = fmaf(-m0, pv, cv0[c]);
                        float v1 = fmaf(-m1, pv, cv1[c]);
                        float v2 = fmaf(-m2, pv, cv2[c]);
                        cv0[c] = v0; cv1[c] = v1; cv2[c] = v2;
                        Fm[nk * FP + lane] = v0;
                        Fm[nk * FP + lane + 32] = v1;
                        if (lane == 0) Fm[nk * FP + 64] = v2;
                        unsigned int key = piv0 ? 0u : pivkey(v0, lane);
                        unsigned int k1  = piv1 ? 0u : pivkey(v1, lane + 32);
                        if (k1 > key) key = k1;
                        if (lane == 0 && !piv2) {
                            unsigned int k2 = pivkey(v2, 64);
                            if (k2 > key) key = k2;
                        }
                        key = __reduce_max_sync(0xffffffffu, key);
                        int prow = (int)(key & 0x7Fu);
                        if (prow < 32) { if (lane == prow)      { pivhist[nk] = prow; dinv[nk] = 1.0f / v0; } }
                        else if (prow < 64) { if (lane == prow - 32) { pivhist[nk] = prow; dinv[nk] = 1.0f / v1; } }
                        else { if (lane == 0)                  { pivhist[nk] = 64;   dinv[nk] = 1.0f / v2; } }
                    }
                }
            }
            #pragma unroll
            for (int c = 0; c < 6; c++) {
                int j = w + 12 * c;
                bool skip = owner && (j == nk);
                if (c < cols0 && j > k && !skip) {
                    float src = (pk < 32) ? cv0[c] : ((pk < 64) ? cv1[c] : cv2[c]);
                    float pv = __shfl_sync(0xffffffffu, src, pk & 31);
                    cv0[c] = fmaf(-m0, pv, cv0[c]);
                    cv1[c] = fmaf(-m1, pv, cv1[c]);
                    cv2[c] = fmaf(-m2, pv, cv2[c]);
                }
            }
            __syncthreads();
        }

        if (w == 5) {        // rhs col 65 lives in warp 5 (c = 5)
            rf[lane] = cv0[5];
            rf[lane + 32] = cv1[5];
            if (lane == 0) rf[64] = cv2[5];
        }
        __syncthreads();
    }

    // ---- direct solution (Jordan) ----
    if (t < NA) wd[t] = (double)(rf[pivhist[t]] * dinv[t]);
    __syncthreads();

    // ---- 1x fp64-residual refinement: rf = -w - H*(u + C*w) ----
    {
        for (int kk = w; kk < NAT; kk += 12) {
            const float* Ar = As + kk * 64;
            double acc = 0.0;
            for (int cc = lane; cc < NAT; cc += 32) acc += (double)Ar[cc] * wd[cc];
            #pragma unroll
            for (int off = 16; off; off >>= 1) acc += __shfl_down_sync(0xffffffffu, acc, off);
            if (lane == 0) cwd[kk] = acc;
        }
        if (t == 0) cwd[64] = -wd[64];
        __syncthreads();
        for (int a = w; a < NA; a += 12) {
            const float* Hr = Hs + a * HP;
            double acc = 0.0;
            for (int k2 = lane; k2 < NA; k2 += 32) {
                double uk = (k2 < 64) ? (double)ens[k2] : (double)q;
                acc += (double)Hr[k2] * (cwd[k2] + uk);
            }
            #pragma unroll
            for (int off = 16; off; off >>= 1) acc += __shfl_down_sync(0xffffffffu, acc, off);
            if (lane == 0) rf[a] = (float)(-wd[a] - acc);
        }
        __syncthreads();
        if (t < 32) {
            float r0 = rf[t];
            float r1 = rf[t + 32];
            float r2 = (t == 0) ? rf[64] : 0.f;
            for (int k = 0; k < NA; k++) {
                int pk = pivhist[k];
                float dk = dinv[k];
                float own = (pk < 32) ? r0 : ((pk < 64) ? r1 : r2);
                float xk = __shfl_sync(0xffffffffu, own, pk & 31);
                if (t != pk)      r0 = fmaf(-(Fm[k * FP + t] * dk), xk, r0);
                if (t + 32 != pk) r1 = fmaf(-(Fm[k * FP + t + 32] * dk), xk, r1);
                if (t == 0 && pk != 64) r2 = fmaf(-(Fm[k * FP + 64] * dk), xk, r2);
            }
            rg[t] = r0; rg[t + 32] = r1;
            if (t == 0) rg[64] = r2;
            __syncwarp();
            for (int i = t; i < NA; i += 32)
                wd[i] += (double)(rg[pivhist[i]] * dinv[i]);
        }
        __syncthreads();
    }

    // ---- output ----
    if (t < NAT) out[mol * NAT + t] = (float)wd[t];
}

extern "C" void kernel_launch(void* const* d_in, const int* in_sizes, int n_in,
                              void* d_out, int out_size)
{
    const float* positions      = (const float*)d_in[0];
    const float* T              = (const float*)d_in[1];
    const float* eneg           = (const float*)d_in[2];
    const float* node_attrs     = (const float*)d_in[3];
    const float* total_charge   = (const float*)d_in[4];
    const float* hardness       = (const float*)d_in[6];
    const float* cov_radii      = (const float*)d_in[7];
    const int*   atomic_numbers = (const int*)d_in[8];
    const int*   edge_index     = (const int*)d_in[9];
    float* out = (float*)d_out;

    int B = in_sizes[4];
    cudaFuncSetAttribute(cheq_kernel, cudaFuncAttributeMaxDynamicSharedMemorySize, SMEM_BYTES);
    cheq_kernel<<<B, NTH, SMEM_BYTES>>>(positions, T, eneg, node_attrs, total_charge,
                                        hardness, cov_radii, atomic_numbers, edge_index, out);
}

// round 13
// speedup vs baseline: 1.1698x; 1.1698x over previous
#include <cuda_runtime.h>
#include <math.h>

typedef unsigned long long ull;

constexpr int NAT = 64;
constexpr int NE  = 512;
constexpr int NA  = 65;
constexpr int NUMEL = 10;
constexpr int CH  = 256;    // chunk width (edges)
constexpr int WCP = 260;    // Wc pitch (floats)
constexpr int HP  = 68;     // Hs pitch
constexpr int KP  = 68;     // Km pitch (16B-aligned rows)
constexpr int FP  = 68;     // Fm pitch
constexpr int NTH = 384;    // 12 warps

// ---- shared memory byte offsets ----
constexpr int OFF_WD  = 0;                       // double wd[65]
constexpr int OFF_CWD = 528;                     // double cwd[65]
constexpr int OFF_WC  = 1584;                    // float Wc[65][260]
constexpr int OFF_KM  = OFF_WC;                  // float Km[65][68]  (aliases Wc)
constexpr int OFF_FM  = OFF_WC + 65*KP*4 + 16;   // float Fm[65][68]  (aliases Wc, after Km)
constexpr int OFF_AS  = OFF_WC + 65*WCP*4;       // float As[64][64]
constexpr int OFF_HS  = OFF_AS + 64*64*4;        // float Hs[65][68]
constexpr int OFF_SA  = OFF_HS + 65*HP*4;        // float sa[512]
constexpr int OFF_PX  = OFF_SA + 2048;
constexpr int OFF_PY  = OFF_PX + 256;
constexpr int OFF_PZ  = OFF_PY + 256;
constexpr int OFF_EN  = OFF_PZ + 256;
constexpr int OFF_DG  = OFF_EN + 256;
constexpr int OFF_RR  = OFF_DG + 256;
constexpr int OFF_RF  = OFF_RR + 256;            // float rf[68]
constexpr int OFF_RG  = OFF_RF + 272;            // float rg[68]
constexpr int OFF_DI  = OFF_RG + 272;            // float dinv[68]
constexpr int OFF_PH  = OFF_DI + 272;            // int pivhist[68]
constexpr int SMEM_BYTES = OFF_PH + 272;         // ~106 KB -> 2 CTAs/SM

static_assert(OFF_FM + 65*FP*4 <= OFF_AS, "Fm must fit in Wc region after Km");

__device__ __forceinline__ ull ffma2(ull a, ull b, ull c) {
    ull d; asm("fma.rn.f32x2 %0, %1, %2, %3;" : "=l"(d) : "l"(a), "l"(b), "l"(c)); return d;
}
__device__ __forceinline__ ull fadd2(ull a, ull b) {
    ull d; asm("add.rn.f32x2 %0, %1, %2;" : "=l"(d) : "l"(a), "l"(b)); return d;
}
__device__ __forceinline__ float2 unpack2(ull v) {
    float2 f; asm("mov.b64 {%0,%1}, %2;" : "=f"(f.x), "=f"(f.y) : "l"(v)); return f;
}
__device__ __forceinline__ ull pack2(float lo, float hi) {
    ull d; asm("mov.b64 %0, {%1, %2};" : "=l"(d) : "f"(lo), "f"(hi)); return d;
}
__device__ __forceinline__ ull dup2(float f) {
    ull d; asm("mov.b64 %0, {%1, %1};" : "=l"(d) : "f"(f)); return d;
}
// monotone packed key: |v| in top 25 bits, row in low 7
__device__ __forceinline__ unsigned int pivkey(float v, int row) {
    return (__float_as_uint(fabsf(v)) & 0xFFFFFF80u) | (unsigned int)row;
}

__global__ __launch_bounds__(NTH, 2)
void cheq_kernel(const float* __restrict__ positions,
                 const float* __restrict__ T,
                 const float* __restrict__ eneg,
                 const float* __restrict__ node_attrs,
                 const float* __restrict__ total_charge,
                 const float* __restrict__ hardness,
                 const float* __restrict__ cov_radii,
                 const int*   __restrict__ atomic_numbers,
                 const int*   __restrict__ edge_index,
                 float* __restrict__ out)
{
    extern __shared__ __align__(16) unsigned char sm[];
    double* wd  = (double*)(sm + OFF_WD);
    double* cwd = (double*)(sm + OFF_CWD);
    float* Wc  = (float*)(sm + OFF_WC);
    float* Km  = (float*)(sm + OFF_KM);
    float* Fm  = (float*)(sm + OFF_FM);
    float* As  = (float*)(sm + OFF_AS);
    float* Hs  = (float*)(sm + OFF_HS);
    float* sa  = (float*)(sm + OFF_SA);
    float* px  = (float*)(sm + OFF_PX);
    float* py  = (float*)(sm + OFF_PY);
    float* pz  = (float*)(sm + OFF_PZ);
    float* ens = (float*)(sm + OFF_EN);
    float* dgs = (float*)(sm + OFF_DG);
    float* rrs = (float*)(sm + OFF_RR);
    float* rf  = (float*)(sm + OFF_RF);
    float* rg  = (float*)(sm + OFF_RG);
    float* dinv= (float*)(sm + OFF_DI);
    int*   pivhist = (int*)(sm + OFF_PH);

    const int mol = blockIdx.x;
    const int t = threadIdx.x;
    const int lane = t & 31;
    const int w = t >> 5;
    const float* Tm = T + (size_t)mol * (NAT * NE);
    const float* pm = positions + mol * NAT * 3;
    const int* eim = edge_index + mol * 2 * NE;
    const float q = total_charge[mol];

    // ---- per-atom small loads ----
    if (t < NAT) {
        px[t] = pm[3*t+0]; py[t] = pm[3*t+1]; pz[t] = pm[3*t+2];
        ens[t] = eneg[mol * NAT + t];
        float r = cov_radii[atomic_numbers[mol * NAT + t]];
        rrs[t] = r * r;
        const float* na = node_attrs + (size_t)(mol * NAT + t) * NUMEL;
        float best = na[0]; int bi = 0;
        #pragma unroll
        for (int j = 1; j < NUMEL; j++) { float v = na[j]; if (v > best) { best = v; bi = j; } }
        dgs[t] = hardness[bi] + 0.5641895835477563f / r;
    }
    __syncthreads();

    // ---- A matrix (64x64, symmetric) ----
    for (int idx = t; idx < NAT * NAT; idx += NTH) {
        int i = idx >> 6, j = idx & 63;
        float v;
        if (i == j) v = dgs[i];
        else {
            float dx = px[i]-px[j], dy = py[i]-py[j], dz = pz[i]-pz[j];
            float d = sqrtf(dx*dx + dy*dy + dz*dz);
            float arg = d * rsqrtf(2.0f * (rrs[i] + rrs[j]));
            v = erff(arg) / d;
        }
        As[idx] = v;
    }

    // ---- edges: sa[e] = sqrt(1/cut), cancellation-free ----
    for (int e = t; e < NE; e += NTH) {
        int a0 = eim[e], a1 = eim[NE + e];
        float dx = px[a0]-px[a1], dy = py[a0]-py[a1], dz = pz[a0]-pz[a1];
        float ed = sqrtf(dx*dx + dy*dy + dz*dz);
        float th = 0.15707963267948966f * ed;
        float sh = sinf(0.5f * th);
        float ct = cosf(th);
        float dv = ct / (2.0f * sh * sh);
        dv = fmaxf(dv, 1e-30f);
        sa[e] = sqrtf(dv);
    }
    __syncthreads();

    // ---- syrk tile geometry (91 triangular 5x5 tiles; 12 warps x 4 groups x 2 rounds) ----
    const int g  = (lane >> 3);
    const int l8 = lane & 7;
    int tiR[2], tjR[2]; bool actR[2];
    #pragma unroll
    for (int r = 0; r < 2; r++) {
        int p = r * 48 + w * 4 + g;
        actR[r] = (p < 91);
        int pp = actR[r] ? p : 0;
        int ti = (int)((sqrtf(8.0f * pp + 1.0f) - 1.0f) * 0.5f);
        while ((ti + 1) * (ti + 2) / 2 <= pp) ++ti;
        while (ti * (ti + 1) / 2 > pp) --ti;
        tiR[r] = ti; tjR[r] = pp - ti * (ti + 1) / 2;
    }

    // ---- chunk loop: H = W W^T ----
    for (int c = 0; c < 2; c++) {
        const int base = c * CH;
        for (int idx = t; idx < 64 * 64; idx += NTH) {
            int a = idx >> 6, e = (idx & 63) * 4;
            float4 v  = *(const float4*)(Tm + a * NE + base + e);
            float4 s4 = *(const float4*)(sa + base + e);
            v.x *= s4.x; v.y *= s4.y; v.z *= s4.z; v.w *= s4.w;
            *(float4*)(Wc + a * WCP + e) = v;
        }
        if (t < 64) *(float4*)(Wc + 64 * WCP + 4*t) = *(const float4*)(sa + base + 4*t);
        __syncthreads();

        #pragma unroll
        for (int r = 0; r < 2; r++) {
            const float* Wa = Wc + (tiR[r] * 5) * WCP;
            const float* Wb = Wc + (tjR[r] * 5) * WCP;
            const bool diag = (tiR[r] == tjR[r]);
            ull acc[25];
            #pragma unroll
            for (int m = 0; m < 25; m++) acc[m] = 0ull;
            for (int e = 4 * l8; e < CH; e += 32) {
                ulonglong2 av[5];
                #pragma unroll
                for (int i = 0; i < 5; i++)
                    av[i] = *(const ulonglong2*)(Wa + i * WCP + e);
                #pragma unroll
                for (int j = 0; j < 5; j++) {
                    ulonglong2 bv = diag ? av[j] : *(const ulonglong2*)(Wb + j * WCP + e);
                    #pragma unroll
                    for (int i = 0; i < 5; i++) {
                        acc[i*5+j] = ffma2(av[i].x, bv.x, acc[i*5+j]);
                        acc[i*5+j] = ffma2(av[i].y, bv.y, acc[i*5+j]);
                    }
                }
            }
            #pragma unroll
            for (int m = 0; m < 25; m++) {
                acc[m] = fadd2(acc[m], __shfl_down_sync(0xffffffffu, acc[m], 4));
                acc[m] = fadd2(acc[m], __shfl_down_sync(0xffffffffu, acc[m], 2));
                acc[m] = fadd2(acc[m], __shfl_down_sync(0xffffffffu, acc[m], 1));
            }
            if (actR[r] && l8 == 0) {
                int ti = tiR[r], tj = tjR[r];
                #pragma unroll
                for (int i = 0; i < 5; i++)
                    #pragma unroll
                    for (int j = 0; j < 5; j++) {
                        float2 f = unpack2(acc[i*5+j]);
                        float v = f.x + f.y;
                        int lo = (ti*5+i) * HP + (tj*5+j);
                        if (c == 0) Hs[lo] = v; else Hs[lo] += v;
                        if (ti != tj) {
                            int up = (tj*5+j) * HP + (ti*5+i);
                            if (c == 0) Hs[up] = v; else Hs[up] += v;
                        }
                    }
            }
        }
        __syncthreads();
    }

    // ---- K = I + H*C; rhs col 65 = -H*u (fp64); col 64 = delta - H col64 ----
    for (int a = w; a < NA; a += 12) {
        const float* Hr = Hs + a * HP;
        double acc = 0.0;
        for (int k2 = lane; k2 < NA; k2 += 32) {
            float uk = (k2 < 64) ? ens[k2] : q;
            acc += (double)Hr[k2] * (double)uk;
        }
        #pragma unroll
        for (int off = 16; off; off >>= 1) acc += __shfl_down_sync(0xffffffffu, acc, off);
        if (lane == 0) Km[a * KP + 65] = (float)(-acc);
    }
    if (t < NA)
        Km[t * KP + 64] = ((t == 64) ? 1.0f : 0.0f) - Hs[t * HP + 64];
    {
        const int half = lane >> 4;
        const int c0 = (lane & 15) * 4;
        #pragma unroll
        for (int pass = 0; pass < 3; pass++) {
            int a = pass * 24 + w * 2 + half;
            if (a < NA) {
                const float* Hr = Hs + a * HP;
                ull acc0 = 0ull, acc1 = 0ull;
                #pragma unroll 4
                for (int k4 = 0; k4 < 16; k4++) {
                    float4 hv = *(const float4*)(Hr + k4 * 4);
                    ulonglong2 a0 = *(const ulonglong2*)(As + (k4*4+0) * 64 + c0);
                    ulonglong2 a1 = *(const ulonglong2*)(As + (k4*4+1) * 64 + c0);
                    ulonglong2 a2 = *(const ulonglong2*)(As + (k4*4+2) * 64 + c0);
                    ulonglong2 a3 = *(const ulonglong2*)(As + (k4*4+3) * 64 + c0);
                    ull h0 = dup2(hv.x), h1 = dup2(hv.y), h2 = dup2(hv.z), h3 = dup2(hv.w);
                    acc0 = ffma2(h0, a0.x, acc0); acc1 = ffma2(h0, a0.y, acc1);
                    acc0 = ffma2(h1, a1.x, acc0); acc1 = ffma2(h1, a1.y, acc1);
                    acc0 = ffma2(h2, a2.x, acc0); acc1 = ffma2(h2, a2.y, acc1);
                    acc0 = ffma2(h3, a3.x, acc0); acc1 = ffma2(h3, a3.y, acc1);
                }
                float2 f0 = unpack2(acc0), f1 = unpack2(acc1);
                float4 v;
                v.x = f0.x + ((a == c0+0) ? 1.0f : 0.0f);
                v.y = f0.y + ((a == c0+1) ? 1.0f : 0.0f);
                v.z = f1.x + ((a == c0+2) ? 1.0f : 0.0f);
                v.w = f1.y + ((a == c0+3) ? 1.0f : 0.0f);
                *(float4*)(Km + a * KP + c0) = v;
            }
        }
    }
    __syncthreads();

    // ---- Gauss-Jordan, register-resident columns (rows lane/lane+32 PACKED f32x2) ----
    {
        const int cols0 = (w < 6) ? 6 : 5;
        ull   cv01[6];     // packed rows (lane, lane+32) per owned column
        float cv2[6];      // row 64 (lane 0 only)
        #pragma unroll
        for (int c = 0; c < 6; c++) {
            cv01[c] = 0ull; cv2[c] = 0.f;
            int j = w + 12 * c;
            if (c < cols0) {
                cv01[c] = pack2(Km[lane * KP + j], Km[(lane + 32) * KP + j]);
                if (lane == 0) cv2[c] = Km[64 * KP + j];
            }
        }
        bool piv0 = false, piv1 = false, piv2 = false;
        if (w == 0) {                           // publish col 0 + select pivot 0
            float2 f = unpack2(cv01[0]);
            Fm[lane] = f.x;
            Fm[lane + 32] = f.y;
            if (lane == 0) Fm[64] = cv2[0];
            unsigned int key = pivkey(f.x, lane);
            unsigned int k1  = pivkey(f.y, lane + 32);
            if (k1 > key) key = k1;
            if (lane == 0) { unsigned int k2 = pivkey(cv2[0], 64); if (k2 > key) key = k2; }
            #pragma unroll
            for (int o = 16; o; o >>= 1) {
                unsigned int ov = __shfl_xor_sync(0xffffffffu, key, o);
                if (ov > key) key = ov;
            }
            int prow = (int)(key & 0x7Fu);
            float src = (prow < 32) ? f.x : ((prow < 64) ? f.y : cv2[0]);
            float pval = __shfl_sync(0xffffffffu, src, prow & 31);
            if (lane == 0) { pivhist[0] = prow; dinv[0] = 1.0f / pval; }
        }
        __syncthreads();

        for (int k = 0; k < NA; k++) {
            int pk = pivhist[k];
            float dk = dinv[k];
            const float* Fk = Fm + k * FP;
            float m0 = Fk[lane] * dk;
            float m1 = Fk[lane + 32] * dk;
            float m2 = Fk[64] * dk;
            if (lane == pk)      { m0 = 0.f; piv0 = true; }
            if (lane + 32 == pk) { m1 = 0.f; piv1 = true; }
            if (pk == 64)        { m2 = 0.f; piv2 = true; }
            ull nm01 = pack2(-m0, -m1);
            #pragma unroll
            for (int c = 0; c < 6; c++) {
                int j = w + 12 * c;
                if (c < cols0 && j > k) {       // warp-uniform predicate
                    float2 f = unpack2(cv01[c]);
                    float src = (pk < 32) ? f.x : ((pk < 64) ? f.y : cv2[c]);
                    float pv = __shfl_sync(0xffffffffu, src, pk & 31);
                    cv01[c] = ffma2(nm01, dup2(pv), cv01[c]);
                    cv2[c]  = fmaf(-m2, pv, cv2[c]);
                }
            }
            int nk = k + 1;
            if (nk < NA && w == (nk % 12)) {    // publish col nk + select pivot nk
                #pragma unroll
                for (int c = 0; c < 6; c++) {
                    if (c < cols0 && (w + 12 * c) == nk) {
                        float2 f = unpack2(cv01[c]);
                        float v2 = cv2[c];
                        Fm[nk * FP + lane] = f.x;
                        Fm[nk * FP + lane + 32] = f.y;
                        if (lane == 0) Fm[nk * FP + 64] = v2;
                        unsigned int key = piv0 ? 0u : pivkey(f.x, lane);
                        unsigned int k1  = piv1 ? 0u : pivkey(f.y, lane + 32);
                        if (k1 > key) key = k1;
                        if (lane == 0 && !piv2) {
                            unsigned int k2 = pivkey(v2, 64);
                            if (k2 > key) key = k2;
                        }
                        #pragma unroll
                        for (int o = 16; o; o >>= 1) {
                            unsigned int ov = __shfl_xor_sync(0xffffffffu, key, o);
                            if (ov > key) key = ov;
                        }
                        int prow = (int)(key & 0x7Fu);
                        float src = (prow < 32) ? f.x : ((prow < 64) ? f.y : v2);
                        float pval = __shfl_sync(0xffffffffu, src, prow & 31);
                        if (lane == 0) { pivhist[nk] = prow; dinv[nk] = 1.0f / pval; }
                    }
                }
            }
            __syncthreads();
        }

        // rhs col 65 lives in warp 5 (c = 5): publish to rf
        if (w == 5) {
            float2 f = unpack2(cv01[5]);
            rf[lane] = f.x;
            rf[lane + 32] = f.y;
            if (lane == 0) rf[64] = cv2[5];
        }
        __syncthreads();
    }

    // ---- direct solution (Jordan) ----
    if (t < NA) wd[t] = (double)(rf[pivhist[t]] * dinv[t]);
    __syncthreads();

    // ---- 1x fp64-residual refinement: rf = -w - H*(u + C*w) ----
    {
        for (int kk = w; kk < NAT; kk += 12) {
            const float* Ar = As + kk * 64;
            double acc = 0.0;
            for (int cc = lane; cc < NAT; cc += 32) acc += (double)Ar[cc] * wd[cc];
            #pragma unroll
            for (int off = 16; off; off >>= 1) acc += __shfl_down_sync(0xffffffffu, acc, off);
            if (lane == 0) cwd[kk] = acc;
        }
        if (t == 0) cwd[64] = -wd[64];
        __syncthreads();
        for (int a = w; a < NA; a += 12) {
            const float* Hr = Hs + a * HP;
            double acc = 0.0;
            for (int k2 = lane; k2 < NA; k2 += 32) {
                double uk = (k2 < 64) ? (double)ens[k2] : (double)q;
                acc += (double)Hr[k2] * (cwd[k2] + uk);
            }
            #pragma unroll
            for (int off = 16; off; off >>= 1) acc += __shfl_down_sync(0xffffffffu, acc, off);
            if (lane == 0) rf[a] = (float)(-wd[a] - acc);
        }
        __syncthreads();
        // apply Jordan factors (from Fm) to residual: register-resident, warp 0
        if (t < 32) {
            float r0 = rf[t];
            float r1 = rf[t + 32];
            float r2 = (t == 0) ? rf[64] : 0.f;
            for (int k = 0; k < NA; k++) {
                int pk = pivhist[k];
                float dk = dinv[k];
                float own = (pk < 32) ? r0 : ((pk < 64) ? r1 : r2);
                float xk = __shfl_sync(0xffffffffu, own, pk & 31);
                if (t != pk)      r0 = fmaf(-(Fm[k * FP + t] * dk), xk, r0);
                if (t + 32 != pk) r1 = fmaf(-(Fm[k * FP + t + 32] * dk), xk, r1);
                if (t == 0 && pk != 64) r2 = fmaf(-(Fm[k * FP + 64] * dk), xk, r2);
            }
            rg[t] = r0; rg[t + 32] = r1;
            if (t == 0) rg[64] = r2;
            __syncwarp();
            for (int i = t; i < NA; i += 32)
                wd[i] += (double)(rg[pivhist[i]] * dinv[i]);
        }
        __syncthreads();
    }

    // ---- output ----
    if (t < NAT) out[mol * NAT + t] = (float)wd[t];
}

extern "C" void kernel_launch(void* const* d_in, const int* in_sizes, int n_in,
                              void* d_out, int out_size)
{
    const float* positions      = (const float*)d_in[0];
    const float* T              = (const float*)d_in[1];
    const float* eneg           = (const float*)d_in[2];
    const float* node_attrs     = (const float*)d_in[3];
    const float* total_charge   = (const float*)d_in[4];
    const float* hardness       = (const float*)d_in[6];
    const float* cov_radii      = (const float*)d_in[7];
    const int*   atomic_numbers = (const int*)d_in[8];
    const int*   edge_index     = (const int*)d_in[9];
    float* out = (float*)d_out;

    int B = in_sizes[4];
    cudaFuncSetAttribute(cheq_kernel, cudaFuncAttributeMaxDynamicSharedMemorySize, SMEM_BYTES);
    cheq_kernel<<<B, NTH, SMEM_BYTES>>>(positions, T, eneg, node_attrs, total_charge,
                                        hardness, cov_radii, atomic_numbers, edge_index, out);
}

// round 14
// speedup vs baseline: 1.5383x; 1.3150x over previous
#include <cuda_runtime.h>
#include <math.h>

typedef unsigned long long ull;

constexpr int NAT = 64;
constexpr int NE  = 512;
constexpr int NA  = 65;
constexpr int NUMEL = 10;
constexpr int CH  = 256;    // chunk width (edges)
constexpr int WCP = 260;    // Wc pitch (floats)
constexpr int HP  = 68;     // Hs pitch
constexpr int KP  = 68;     // Km pitch (16B-aligned rows)
constexpr int FP  = 68;     // Fm pitch
constexpr int NTH = 384;    // 12 warps

// ---- shared memory byte offsets ----
constexpr int OFF_WC  = 0;                       // float Wc[65][260]
constexpr int OFF_KM  = OFF_WC;                  // float Km[65][68]  (aliases Wc)
constexpr int OFF_FM  = OFF_WC + 65*KP*4 + 16;   // float Fm[65][68]  (aliases Wc, after Km)
constexpr int OFF_AS  = OFF_WC + 65*WCP*4;       // float As[64][64]
constexpr int OFF_HS  = OFF_AS + 64*64*4;        // float Hs[65][68]
constexpr int OFF_SA  = OFF_HS + 65*HP*4;        // float sa[512]
constexpr int OFF_PX  = OFF_SA + 2048;
constexpr int OFF_PY  = OFF_PX + 256;
constexpr int OFF_PZ  = OFF_PY + 256;
constexpr int OFF_EN  = OFF_PZ + 256;
constexpr int OFF_DG  = OFF_EN + 256;
constexpr int OFF_RR  = OFF_DG + 256;
constexpr int OFF_RF  = OFF_RR + 256;            // float rf[68]
constexpr int OFF_DI  = OFF_RF + 272;            // float dinv[68]
constexpr int OFF_PH  = OFF_DI + 272;            // int pivhist[68]
constexpr int SMEM_BYTES = OFF_PH + 272;         // ~104 KB -> 2 CTAs/SM

static_assert(OFF_FM + 65*FP*4 <= OFF_AS, "Fm must fit in Wc region after Km");

__device__ __forceinline__ ull ffma2(ull a, ull b, ull c) {
    ull d; asm("fma.rn.f32x2 %0, %1, %2, %3;" : "=l"(d) : "l"(a), "l"(b), "l"(c)); return d;
}
__device__ __forceinline__ ull fadd2(ull a, ull b) {
    ull d; asm("add.rn.f32x2 %0, %1, %2;" : "=l"(d) : "l"(a), "l"(b)); return d;
}
__device__ __forceinline__ float2 unpack2(ull v) {
    float2 f; asm("mov.b64 {%0,%1}, %2;" : "=f"(f.x), "=f"(f.y) : "l"(v)); return f;
}
__device__ __forceinline__ ull dup2(float f) {
    ull d; asm("mov.b64 %0, {%1, %1};" : "=l"(d) : "f"(f)); return d;
}
// monotone packed key: |v| in top 25 bits, row in low 7
__device__ __forceinline__ unsigned int pivkey(float v, int row) {
    return (__float_as_uint(fabsf(v)) & 0xFFFFFF80u) | (unsigned int)row;
}

__global__ __launch_bounds__(NTH, 2)
void cheq_kernel(const float* __restrict__ positions,
                 const float* __restrict__ T,
                 const float* __restrict__ eneg,
                 const float* __restrict__ node_attrs,
                 const float* __restrict__ total_charge,
                 const float* __restrict__ hardness,
                 const float* __restrict__ cov_radii,
                 const int*   __restrict__ atomic_numbers,
                 const int*   __restrict__ edge_index,
                 float* __restrict__ out)
{
    extern __shared__ __align__(16) unsigned char sm[];
    float* Wc  = (float*)(sm + OFF_WC);
    float* Km  = (float*)(sm + OFF_KM);
    float* Fm  = (float*)(sm + OFF_FM);
    float* As  = (float*)(sm + OFF_AS);
    float* Hs  = (float*)(sm + OFF_HS);
    float* sa  = (float*)(sm + OFF_SA);
    float* px  = (float*)(sm + OFF_PX);
    float* py  = (float*)(sm + OFF_PY);
    float* pz  = (float*)(sm + OFF_PZ);
    float* ens = (float*)(sm + OFF_EN);
    float* dgs = (float*)(sm + OFF_DG);
    float* rrs = (float*)(sm + OFF_RR);
    float* rf  = (float*)(sm + OFF_RF);
    float* dinv= (float*)(sm + OFF_DI);
    int*   pivhist = (int*)(sm + OFF_PH);

    const int mol = blockIdx.x;
    const int t = threadIdx.x;
    const int lane = t & 31;
    const int w = t >> 5;
    const float* Tm = T + (size_t)mol * (NAT * NE);
    const float* pm = positions + mol * NAT * 3;
    const int* eim = edge_index + mol * 2 * NE;
    const float q = total_charge[mol];

    // ---- per-atom small loads ----
    if (t < NAT) {
        px[t] = pm[3*t+0]; py[t] = pm[3*t+1]; pz[t] = pm[3*t+2];
        ens[t] = eneg[mol * NAT + t];
        float r = cov_radii[atomic_numbers[mol * NAT + t]];
        rrs[t] = r * r;
        const float* na = node_attrs + (size_t)(mol * NAT + t) * NUMEL;
        float best = na[0]; int bi = 0;
        #pragma unroll
        for (int j = 1; j < NUMEL; j++) { float v = na[j]; if (v > best) { best = v; bi = j; } }
        dgs[t] = hardness[bi] + 0.5641895835477563f / r;
    }
    __syncthreads();

    // ---- A matrix (64x64, symmetric) ----
    for (int idx = t; idx < NAT * NAT; idx += NTH) {
        int i = idx >> 6, j = idx & 63;
        float v;
        if (i == j) v = dgs[i];
        else {
            float dx = px[i]-px[j], dy = py[i]-py[j], dz = pz[i]-pz[j];
            float d = sqrtf(dx*dx + dy*dy + dz*dz);
            float arg = d * rsqrtf(2.0f * (rrs[i] + rrs[j]));
            v = erff(arg) / d;
        }
        As[idx] = v;
    }

    // ---- edges: sa[e] = sqrt(1/cut), cancellation-free ----
    for (int e = t; e < NE; e += NTH) {
        int a0 = eim[e], a1 = eim[NE + e];
        float dx = px[a0]-px[a1], dy = py[a0]-py[a1], dz = pz[a0]-pz[a1];
        float ed = sqrtf(dx*dx + dy*dy + dz*dz);
        float th = 0.15707963267948966f * ed;
        float sh = sinf(0.5f * th);
        float ct = cosf(th);
        float dv = ct / (2.0f * sh * sh);
        dv = fmaxf(dv, 1e-30f);
        sa[e] = sqrtf(dv);
    }
    __syncthreads();

    // ---- syrk tile geometry (91 triangular 5x5 tiles; 12 warps x 4 groups x 2 rounds) ----
    const int g  = (lane >> 3);
    const int l8 = lane & 7;
    int tiR[2], tjR[2]; bool actR[2];
    #pragma unroll
    for (int r = 0; r < 2; r++) {
        int p = r * 48 + w * 4 + g;
        actR[r] = (p < 91);
        int pp = actR[r] ? p : 0;
        int ti = (int)((sqrtf(8.0f * pp + 1.0f) - 1.0f) * 0.5f);
        while ((ti + 1) * (ti + 2) / 2 <= pp) ++ti;
        while (ti * (ti + 1) / 2 > pp) --ti;
        tiR[r] = ti; tjR[r] = pp - ti * (ti + 1) / 2;
    }

    // ---- chunk loop: H = W W^T ----
    for (int c = 0; c < 2; c++) {
        const int base = c * CH;
        for (int idx = t; idx < 64 * 64; idx += NTH) {
            int a = idx >> 6, e = (idx & 63) * 4;
            float4 v  = *(const float4*)(Tm + a * NE + base + e);
            float4 s4 = *(const float4*)(sa + base + e);
            v.x *= s4.x; v.y *= s4.y; v.z *= s4.z; v.w *= s4.w;
            *(float4*)(Wc + a * WCP + e) = v;
        }
        if (t < 64) *(float4*)(Wc + 64 * WCP + 4*t) = *(const float4*)(sa + base + 4*t);
        __syncthreads();

        #pragma unroll
        for (int r = 0; r < 2; r++) {
            const float* Wa = Wc + (tiR[r] * 5) * WCP;
            const float* Wb = Wc + (tjR[r] * 5) * WCP;
            const bool diag = (tiR[r] == tjR[r]);
            ull acc[25];
            #pragma unroll
            for (int m = 0; m < 25; m++) acc[m] = 0ull;
            for (int e = 4 * l8; e < CH; e += 32) {
                ulonglong2 av[5];
                #pragma unroll
                for (int i = 0; i < 5; i++)
                    av[i] = *(const ulonglong2*)(Wa + i * WCP + e);
                #pragma unroll
                for (int j = 0; j < 5; j++) {
                    ulonglong2 bv = diag ? av[j] : *(const ulonglong2*)(Wb + j * WCP + e);
                    #pragma unroll
                    for (int i = 0; i < 5; i++) {
                        acc[i*5+j] = ffma2(av[i].x, bv.x, acc[i*5+j]);
                        acc[i*5+j] = ffma2(av[i].y, bv.y, acc[i*5+j]);
                    }
                }
            }
            #pragma unroll
            for (int m = 0; m < 25; m++) {
                acc[m] = fadd2(acc[m], __shfl_down_sync(0xffffffffu, acc[m], 4));
                acc[m] = fadd2(acc[m], __shfl_down_sync(0xffffffffu, acc[m], 2));
                acc[m] = fadd2(acc[m], __shfl_down_sync(0xffffffffu, acc[m], 1));
            }
            if (actR[r] && l8 == 0) {
                int ti = tiR[r], tj = tjR[r];
                #pragma unroll
                for (int i = 0; i < 5; i++)
                    #pragma unroll
                    for (int j = 0; j < 5; j++) {
                        float2 f = unpack2(acc[i*5+j]);
                        float v = f.x + f.y;
                        int lo = (ti*5+i) * HP + (tj*5+j);
                        if (c == 0) Hs[lo] = v; else Hs[lo] += v;
                        if (ti != tj) {
                            int up = (tj*5+j) * HP + (ti*5+i);
                            if (c == 0) Hs[up] = v; else Hs[up] += v;
                        }
                    }
            }
        }
        __syncthreads();
    }

    // ---- K = I + H*C; rhs col 65 = -H*u (fp64); col 64 = delta - H col64 ----
    for (int a = w; a < NA; a += 12) {
        const float* Hr = Hs + a * HP;
        double acc = 0.0;
        for (int k2 = lane; k2 < NA; k2 += 32) {
            float uk = (k2 < 64) ? ens[k2] : q;
            acc += (double)Hr[k2] * (double)uk;
        }
        #pragma unroll
        for (int off = 16; off; off >>= 1) acc += __shfl_down_sync(0xffffffffu, acc, off);
        if (lane == 0) Km[a * KP + 65] = (float)(-acc);
    }
    if (t < NA)
        Km[t * KP + 64] = ((t == 64) ? 1.0f : 0.0f) - Hs[t * HP + 64];
    {
        const int half = lane >> 4;
        const int c0 = (lane & 15) * 4;
        #pragma unroll
        for (int pass = 0; pass < 3; pass++) {
            int a = pass * 24 + w * 2 + half;
            if (a < NA) {
                const float* Hr = Hs + a * HP;
                ull acc0 = 0ull, acc1 = 0ull;
                #pragma unroll 4
                for (int k4 = 0; k4 < 16; k4++) {
                    float4 hv = *(const float4*)(Hr + k4 * 4);
                    ulonglong2 a0 = *(const ulonglong2*)(As + (k4*4+0) * 64 + c0);
                    ulonglong2 a1 = *(const ulonglong2*)(As + (k4*4+1) * 64 + c0);
                    ulonglong2 a2 = *(const ulonglong2*)(As + (k4*4+2) * 64 + c0);
                    ulonglong2 a3 = *(const ulonglong2*)(As + (k4*4+3) * 64 + c0);
                    ull h0 = dup2(hv.x), h1 = dup2(hv.y), h2 = dup2(hv.z), h3 = dup2(hv.w);
                    acc0 = ffma2(h0, a0.x, acc0); acc1 = ffma2(h0, a0.y, acc1);
                    acc0 = ffma2(h1, a1.x, acc0); acc1 = ffma2(h1, a1.y, acc1);
                    acc0 = ffma2(h2, a2.x, acc0); acc1 = ffma2(h2, a2.y, acc1);
                    acc0 = ffma2(h3, a3.x, acc0); acc1 = ffma2(h3, a3.y, acc1);
                }
                float2 f0 = unpack2(acc0), f1 = unpack2(acc1);
                float4 v;
                v.x = f0.x + ((a == c0+0) ? 1.0f : 0.0f);
                v.y = f0.y + ((a == c0+1) ? 1.0f : 0.0f);
                v.z = f1.x + ((a == c0+2) ? 1.0f : 0.0f);
                v.w = f1.y + ((a == c0+3) ? 1.0f : 0.0f);
                *(float4*)(Km + a * KP + c0) = v;
            }
        }
    }
    __syncthreads();

    // ---- Gauss-Jordan, register-resident columns, shfl pivot rows ----
    {
        const int cols0 = (w < 6) ? 6 : 5;
        float cv0[6], cv1[6], cv2[6];
        #pragma unroll
        for (int c = 0; c < 6; c++) {
            cv0[c] = 0.f; cv1[c] = 0.f; cv2[c] = 0.f;
            int j = w + 12 * c;
            if (c < cols0) {
                cv0[c] = Km[lane * KP + j];
                cv1[c] = Km[(lane + 32) * KP + j];
                if (lane == 0) cv2[c] = Km[64 * KP + j];
            }
        }
        bool piv0 = false, piv1 = false, piv2 = false;
        if (w == 0) {                           // publish col 0 + select pivot 0
            Fm[lane] = cv0[0];
            Fm[lane + 32] = cv1[0];
            if (lane == 0) Fm[64] = cv2[0];
            unsigned int key = pivkey(cv0[0], lane);
            unsigned int k1  = pivkey(cv1[0], lane + 32);
            if (k1 > key) key = k1;
            if (lane == 0) { unsigned int k2 = pivkey(cv2[0], 64); if (k2 > key) key = k2; }
            #pragma unroll
            for (int o = 16; o; o >>= 1) {
                unsigned int ov = __shfl_xor_sync(0xffffffffu, key, o);
                if (ov > key) key = ov;
            }
            int prow = (int)(key & 0x7Fu);
            float src = (prow < 32) ? cv0[0] : ((prow < 64) ? cv1[0] : cv2[0]);
            float pval = __shfl_sync(0xffffffffu, src, prow & 31);
            if (lane == 0) { pivhist[0] = prow; dinv[0] = 1.0f / pval; }
        }
        __syncthreads();

        for (int k = 0; k < NA; k++) {
            int pk = pivhist[k];
            float dk = dinv[k];
            float m0 = Fm[k * FP + lane] * dk;
            float m1 = Fm[k * FP + lane + 32] * dk;
            float m2 = Fm[k * FP + 64] * dk;
            if (lane == pk)      { m0 = 0.f; piv0 = true; }
            if (lane + 32 == pk) { m1 = 0.f; piv1 = true; }
            if (pk == 64)        { m2 = 0.f; piv2 = true; }
            #pragma unroll
            for (int c = 0; c < 6; c++) {
                int j = w + 12 * c;
                if (c < cols0 && j > k) {       // warp-uniform predicate
                    float src = (pk < 32) ? cv0[c] : ((pk < 64) ? cv1[c] : cv2[c]);
                    float pv = __shfl_sync(0xffffffffu, src, pk & 31);
                    cv0[c] = fmaf(-m0, pv, cv0[c]);
                    cv1[c] = fmaf(-m1, pv, cv1[c]);
                    cv2[c] = fmaf(-m2, pv, cv2[c]);
                }
            }
            int nk = k + 1;
            if (nk < NA && w == (nk % 12)) {    // publish col nk + select pivot nk
                #pragma unroll
                for (int c = 0; c < 6; c++) {
                    if (c < cols0 && (w + 12 * c) == nk) {
                        float v0 = cv0[c], v1 = cv1[c], v2 = cv2[c];
                        Fm[nk * FP + lane] = v0;
                        Fm[nk * FP + lane + 32] = v1;
                        if (lane == 0) Fm[nk * FP + 64] = v2;
                        unsigned int key = piv0 ? 0u : pivkey(v0, lane);
                        unsigned int k1  = piv1 ? 0u : pivkey(v1, lane + 32);
                        if (k1 > key) key = k1;
                        if (lane == 0 && !piv2) {
                            unsigned int k2 = pivkey(v2, 64);
                            if (k2 > key) key = k2;
                        }
                        #pragma unroll
                        for (int o = 16; o; o >>= 1) {
                            unsigned int ov = __shfl_xor_sync(0xffffffffu, key, o);
                            if (ov > key) key = ov;
                        }
                        int prow = (int)(key & 0x7Fu);
                        float src = (prow < 32) ? v0 : ((prow < 64) ? v1 : v2);
                        float pval = __shfl_sync(0xffffffffu, src, prow & 31);
                        if (lane == 0) { pivhist[nk] = prow; dinv[nk] = 1.0f / pval; }
                    }
                }
            }
            __syncthreads();
        }

        // rhs col 65 lives in warp 5 (c = 5): publish to rf
        if (w == 5) {
            rf[lane] = cv0[5];
            rf[lane + 32] = cv1[5];
            if (lane == 0) rf[64] = cv2[5];
        }
        __syncthreads();
    }

    // ---- direct solution (Jordan; no back-substitution, no refinement) ----
    if (t < NAT) out[mol * NAT + t] = rf[pivhist[t]] * dinv[t];
}

extern "C" void kernel_launch(void* const* d_in, const int* in_sizes, int n_in,
                              void* d_out, int out_size)
{
    const float* positions      = (const float*)d_in[0];
    const float* T              = (const float*)d_in[1];
    const float* eneg           = (const float*)d_in[2];
    const float* node_attrs     = (const float*)d_in[3];
    const float* total_charge   = (const float*)d_in[4];
    const float* hardness       = (const float*)d_in[6];
    const float* cov_radii      = (const float*)d_in[7];
    const int*   atomic_numbers = (const int*)d_in[8];
    const int*   edge_index     = (const int*)d_in[9];
    float* out = (float*)d_out;

    int B = in_sizes[4];
    cudaFuncSetAttribute(cheq_kernel, cudaFuncAttributeMaxDynamicSharedMemorySize, SMEM_BYTES);
    cheq_kernel<<<B, NTH, SMEM_BYTES>>>(positions, T, eneg, node_attrs, total_charge,
                                        hardness, cov_radii, atomic_numbers, edge_index, out);
}